// round 3
// baseline (speedup 1.0000x reference)
#include <cuda_runtime.h>
#include <cuda_bf16.h>
#include <cstdint>

#define B_  4
#define NV_ 4096
#define NT_ 1024
#define TD_ 1024
#define H_  8
#define D_  128

// ------------------------- scratch (device globals) -------------------------
__device__ __align__(256) __nv_bfloat16 g_Vh[(size_t)B_*NV_*TD_];
__device__ __align__(256) __nv_bfloat16 g_Vl[(size_t)B_*NV_*TD_];
__device__ __align__(256) __nv_bfloat16 g_Th[(size_t)B_*NT_*TD_];
__device__ __align__(256) __nv_bfloat16 g_Tl[(size_t)B_*NT_*TD_];
__device__ __align__(256) __nv_bfloat16 g_Wh[(size_t)TD_*TD_];
__device__ __align__(256) __nv_bfloat16 g_Wl[(size_t)TD_*TD_];
__device__ __align__(256) __nv_bfloat16 g_Kh[(size_t)B_*NV_*TD_];
__device__ __align__(256) __nv_bfloat16 g_Kl[(size_t)B_*NV_*TD_];
__device__ __align__(256) __nv_bfloat16 g_KTh[(size_t)B_*H_*D_*NV_];
__device__ __align__(256) __nv_bfloat16 g_KTl[(size_t)B_*H_*D_*NV_];
__device__ __align__(256) __nv_bfloat16 g_Ph[(size_t)B_*H_*NT_*NV_];
__device__ __align__(256) __nv_bfloat16 g_Pl[(size_t)B_*H_*NT_*NV_];

// ------------------------------- helpers ------------------------------------
__device__ __forceinline__ uint32_t smem_u32(const void* p){
    uint32_t a;
    asm("{ .reg .u64 t; cvta.to.shared.u64 t, %1; cvt.u32.u64 %0, t; }" : "=r"(a) : "l"(p));
    return a;
}
__device__ __forceinline__ void cp16(uint32_t dst, const void* src){
    asm volatile("cp.async.cg.shared.global [%0], [%1], 16;" :: "r"(dst), "l"(src));
}
__device__ __forceinline__ void ldsm4(uint32_t* r, uint32_t addr){
    asm volatile("ldmatrix.sync.aligned.m8n8.x4.shared.b16 {%0,%1,%2,%3}, [%4];"
                 : "=r"(r[0]), "=r"(r[1]), "=r"(r[2]), "=r"(r[3]) : "r"(addr));
}
__device__ __forceinline__ void mma16816(float* c, const uint32_t* a, const uint32_t* b){
    asm volatile("mma.sync.aligned.m16n8k16.row.col.f32.bf16.bf16.f32 "
                 "{%0,%1,%2,%3}, {%4,%5,%6,%7}, {%8,%9}, {%0,%1,%2,%3};"
                 : "+f"(c[0]), "+f"(c[1]), "+f"(c[2]), "+f"(c[3])
                 : "r"(a[0]), "r"(a[1]), "r"(a[2]), "r"(a[3]), "r"(b[0]), "r"(b[1]));
}
__device__ __forceinline__ void split2(float x, float y, uint32_t& hp, uint32_t& lp){
    __nv_bfloat16 h0 = __float2bfloat16(x), h1 = __float2bfloat16(y);
    __nv_bfloat16 l0 = __float2bfloat16(x - __bfloat162float(h0));
    __nv_bfloat16 l1 = __float2bfloat16(y - __bfloat162float(h1));
    hp = (uint32_t)__bfloat16_as_ushort(h0) | ((uint32_t)__bfloat16_as_ushort(h1) << 16);
    lp = (uint32_t)__bfloat16_as_ushort(l0) | ((uint32_t)__bfloat16_as_ushort(l1) << 16);
}

// ------------------------- fp32 -> bf16 hi/lo split --------------------------
__global__ void split_kernel(const float* __restrict__ s, __nv_bfloat16* __restrict__ h,
                             __nv_bfloat16* __restrict__ l, long long n4){
    long long i = (long long)blockIdx.x * blockDim.x + threadIdx.x;
    long long stride = (long long)gridDim.x * blockDim.x;
    for (; i < n4; i += stride){
        float4 f = reinterpret_cast<const float4*>(s)[i];
        uint32_t h0, l0, h1, l1;
        split2(f.x, f.y, h0, l0);
        split2(f.z, f.w, h1, l1);
        reinterpret_cast<uint2*>(h)[i] = make_uint2(h0, h1);
        reinterpret_cast<uint2*>(l)[i] = make_uint2(l0, l1);
    }
}

// ---------------------------------------------------------------------------
// bf16 split-3 GEMM: C[128m,128n] (+= over K) = (Ah+Al)[M,K] * (Bh+Bl)[N,K]^T
// Both operands K-major. C fp32, or bf16 hi/lo pair (GEMM1).
// 256 threads = 8 warps (2m x 4n), warp tile 64x32, K-chunk 64, 2-stage cp.async.
// ---------------------------------------------------------------------------
struct GemmArgs {
    const __nv_bfloat16 *Ah, *Al, *Bh, *Bl;
    float* C; __nv_bfloat16 *Ch, *Cl;
    long long lda, ldb, ldc;
    long long sAb, sAh, sBb, sBh, sCb, sCh;
    int K, HZ;
};

#define T_AH 0
#define T_AL 16384
#define T_BH 32768
#define T_BL 49152
#define STAGE 65536
#define SMEM_GEMM (2*STAGE)

__global__ void __launch_bounds__(256, 1) gemm_bf16split(GemmArgs g){
    extern __shared__ char smem[];
    const uint32_t sb = smem_u32(smem);
    const int tid = threadIdx.x;
    const int lane = tid & 31, wid = tid >> 5;
    const int wm = wid >> 2, wn = wid & 3;

    const int zb = blockIdx.z / g.HZ, zh = blockIdx.z % g.HZ;
    const long long m0 = (long long)blockIdx.x << 7;
    const long long n0 = (long long)blockIdx.y << 7;
    const __nv_bfloat16* Ah = g.Ah + (long long)zb*g.sAb + (long long)zh*g.sAh + m0*g.lda;
    const __nv_bfloat16* Al = g.Al + (long long)zb*g.sAb + (long long)zh*g.sAh + m0*g.lda;
    const __nv_bfloat16* Bh = g.Bh + (long long)zb*g.sBb + (long long)zh*g.sBh + n0*g.ldb;
    const __nv_bfloat16* Bl = g.Bl + (long long)zb*g.sBb + (long long)zh*g.sBh + n0*g.ldb;

    // cp.async mapping (per stage: 4 tiles x 128 rows x 8 granules of 16B)
    const int c_row = tid >> 3;        // base row for i=0
    const int c_gc  = tid & 7;

    float acc[4][4][4];
    #pragma unroll
    for (int a = 0; a < 4; ++a)
        #pragma unroll
        for (int b = 0; b < 4; ++b)
            #pragma unroll
            for (int c = 0; c < 4; ++c) acc[a][b][c] = 0.f;

    const int nkt = g.K >> 6;

    // ---- stage loader ----
    #define LOAD_STAGE(S, K0)                                                        \
    do {                                                                             \
        const uint32_t sbs = sb + (uint32_t)(S)*STAGE;                               \
        _Pragma("unroll")                                                            \
        for (int i_ = 0; i_ < 4; ++i_){                                              \
            int row = c_row + (i_ << 5);                                             \
            uint32_t off = (uint32_t)(row << 7) + (uint32_t)((c_gc ^ (row & 7)) << 4);\
            long long ea = (long long)row * g.lda + (K0) + (c_gc << 3);              \
            long long eb = (long long)row * g.ldb + (K0) + (c_gc << 3);              \
            cp16(sbs + T_AH + off, Ah + ea);                                         \
            cp16(sbs + T_AL + off, Al + ea);                                         \
            cp16(sbs + T_BH + off, Bh + eb);                                         \
            cp16(sbs + T_BL + off, Bl + eb);                                         \
        }                                                                            \
    } while (0)

    LOAD_STAGE(0, 0LL);
    asm volatile("cp.async.commit_group;" ::: "memory");

    for (int kt = 0; kt < nkt; ++kt){
        if (kt + 1 < nkt) LOAD_STAGE((kt + 1) & 1, (long long)(kt + 1) << 6);
        asm volatile("cp.async.commit_group;" ::: "memory");
        asm volatile("cp.async.wait_group 1;" ::: "memory");
        __syncthreads();

        const uint32_t st = sb + (uint32_t)(kt & 1)*STAGE;
        #pragma unroll
        for (int s16 = 0; s16 < 4; ++s16){
            uint32_t afh[4][4], afl[4][4];
            const int arow0 = (wm << 6) + (lane & 15);
            const int ahalf = lane >> 4;
            #pragma unroll
            for (int mb = 0; mb < 4; ++mb){
                int row = arow0 + (mb << 4);
                uint32_t gc = (uint32_t)(((s16 << 1) + ahalf) ^ (row & 7));
                uint32_t ad = st + (uint32_t)(row << 7) + (gc << 4);
                ldsm4(afh[mb], ad + T_AH);
                ldsm4(afl[mb], ad + T_AL);
            }
            uint32_t bfh[4][2], bfl[4][2];
            const int brow_ = (lane & 7) + ((lane >> 4) << 3);
            const int bhalf = (lane >> 3) & 1;
            #pragma unroll
            for (int bg = 0; bg < 2; ++bg){
                int row = (wn << 5) + (bg << 4) + brow_;
                uint32_t gc = (uint32_t)(((s16 << 1) + bhalf) ^ (row & 7));
                uint32_t bd = st + (uint32_t)(row << 7) + (gc << 4);
                uint32_t rh[4], rl[4];
                ldsm4(rh, bd + T_BH);
                ldsm4(rl, bd + T_BL);
                bfh[bg*2+0][0] = rh[0]; bfh[bg*2+0][1] = rh[1];
                bfh[bg*2+1][0] = rh[2]; bfh[bg*2+1][1] = rh[3];
                bfl[bg*2+0][0] = rl[0]; bfl[bg*2+0][1] = rl[1];
                bfl[bg*2+1][0] = rl[2]; bfl[bg*2+1][1] = rl[3];
            }
            #pragma unroll
            for (int mb = 0; mb < 4; ++mb)
                #pragma unroll
                for (int nb = 0; nb < 4; ++nb){
                    mma16816(acc[mb][nb], afh[mb], bfh[nb]);
                    mma16816(acc[mb][nb], afh[mb], bfl[nb]);
                    mma16816(acc[mb][nb], afl[mb], bfh[nb]);
                }
        }
        __syncthreads();
    }
    #undef LOAD_STAGE

    // ---- epilogue ----
    const int trow = lane >> 2, tcol = (lane & 3) << 1;
    const long long cbase = (long long)zb*g.sCb + (long long)zh*g.sCh;
    #pragma unroll
    for (int mb = 0; mb < 4; ++mb){
        #pragma unroll
        for (int nb = 0; nb < 4; ++nb){
            long long r0 = m0 + (wm << 6) + (mb << 4) + trow;
            long long cc = n0 + (wn << 5) + (nb << 3) + tcol;
            float* a4 = acc[mb][nb];
            if (g.C){
                float2 v0 = make_float2(a4[0], a4[1]);
                float2 v1 = make_float2(a4[2], a4[3]);
                *reinterpret_cast<float2*>(g.C + cbase + r0*g.ldc + cc) = v0;
                *reinterpret_cast<float2*>(g.C + cbase + (r0+8)*g.ldc + cc) = v1;
            } else {
                uint32_t hp, lp;
                split2(a4[0], a4[1], hp, lp);
                *reinterpret_cast<uint32_t*>(g.Ch + cbase + r0*g.ldc + cc) = hp;
                *reinterpret_cast<uint32_t*>(g.Cl + cbase + r0*g.ldc + cc) = lp;
                split2(a4[2], a4[3], hp, lp);
                *reinterpret_cast<uint32_t*>(g.Ch + cbase + (r0+8)*g.ldc + cc) = hp;
                *reinterpret_cast<uint32_t*>(g.Cl + cbase + (r0+8)*g.ldc + cc) = lp;
            }
        }
    }
}

// ------------- per-head transpose: k[(b*NV+j), h*D+d] -> kT[(bh*D+d), j] -----
__global__ void transpose_bf16_kernel(const __nv_bfloat16* __restrict__ src,
                                      __nv_bfloat16* __restrict__ dst){
    __shared__ __nv_bfloat16 tile[32][33];
    const int bh = blockIdx.z;
    const int b = bh >> 3, h = bh & 7;
    const int j0 = blockIdx.x << 5;
    const int d0 = blockIdx.y << 5;
    const int tx = threadIdx.x, ty = threadIdx.y;
    const __nv_bfloat16* s = src + ((long long)b*NV_)*TD_ + (long long)h*D_;
    #pragma unroll
    for (int i = 0; i < 32; i += 8)
        tile[ty + i][tx] = s[(long long)(j0 + ty + i)*TD_ + d0 + tx];
    __syncthreads();
    __nv_bfloat16* d = dst + ((long long)bh*D_)*NV_;
    #pragma unroll
    for (int i = 0; i < 32; i += 8)
        d[(long long)(d0 + ty + i)*NV_ + j0 + tx] = tile[tx][ty + i];
}

// -------- softmax over 4096 cols, in place + bf16 hi/lo split emission ------
__global__ void softmax_split_kernel(float* __restrict__ attn,
                                     __nv_bfloat16* __restrict__ ph,
                                     __nv_bfloat16* __restrict__ pl){
    __shared__ float red[256];
    const long long row = blockIdx.x;
    float* p = attn + row * 4096;
    __nv_bfloat16* hh = ph + row * 4096;
    __nv_bfloat16* ll = pl + row * 4096;
    const int t = threadIdx.x;
    float v[16];
    float mx = -3.402823466e38f;
    #pragma unroll
    for (int i = 0; i < 16; ++i){ v[i] = p[t + i*256]; mx = fmaxf(mx, v[i]); }
    red[t] = mx; __syncthreads();
    #pragma unroll
    for (int s = 128; s > 0; s >>= 1){
        if (t < s) red[t] = fmaxf(red[t], red[t + s]);
        __syncthreads();
    }
    mx = red[0]; __syncthreads();
    float sum = 0.f;
    #pragma unroll
    for (int i = 0; i < 16; ++i){ v[i] = expf(v[i] - mx); sum += v[i]; }
    red[t] = sum; __syncthreads();
    #pragma unroll
    for (int s = 128; s > 0; s >>= 1){
        if (t < s) red[t] += red[t + s];
        __syncthreads();
    }
    const float inv = 1.0f / red[0];
    #pragma unroll
    for (int i = 0; i < 16; ++i){
        float a = v[i] * inv;
        p[t + i*256] = a;
        __nv_bfloat16 h = __float2bfloat16(a);
        hh[t + i*256] = h;
        ll[t + i*256] = __float2bfloat16(a - __bfloat162float(h));
    }
}

// ---------------------------------------------------------------------------
extern "C" void kernel_launch(void* const* d_in, const int* in_sizes, int n_in,
                              void* d_out, int out_size){
    const float* vis = (const float*)d_in[0];   // [B, NV, 1024]
    const float* txt = (const float*)d_in[1];   // [B, NT, 1024]
    const float* W   = (const float*)d_in[2];   // [1024, 1024]
    float* out  = (float*)d_out;                          // [B, NT, TD]
    float* attn = out + (size_t)B_*NT_*TD_;               // [B, H, NT, NV]

    void *pVh,*pVl,*pTh,*pTl,*pWh,*pWl,*pKh,*pKl,*pKTh,*pKTl,*pPh,*pPl;
    cudaGetSymbolAddress(&pVh, g_Vh);  cudaGetSymbolAddress(&pVl, g_Vl);
    cudaGetSymbolAddress(&pTh, g_Th);  cudaGetSymbolAddress(&pTl, g_Tl);
    cudaGetSymbolAddress(&pWh, g_Wh);  cudaGetSymbolAddress(&pWl, g_Wl);
    cudaGetSymbolAddress(&pKh, g_Kh);  cudaGetSymbolAddress(&pKl, g_Kl);
    cudaGetSymbolAddress(&pKTh, g_KTh); cudaGetSymbolAddress(&pKTl, g_KTl);
    cudaGetSymbolAddress(&pPh, g_Ph);  cudaGetSymbolAddress(&pPl, g_Pl);

    cudaFuncSetAttribute(gemm_bf16split,
                         cudaFuncAttributeMaxDynamicSharedMemorySize, SMEM_GEMM);

    // Split inputs to bf16 hi/lo
    split_kernel<<<8192, 256>>>(vis, (__nv_bfloat16*)pVh, (__nv_bfloat16*)pVl, (long long)B_*NV_*TD_/4);
    split_kernel<<<4096, 256>>>(txt, (__nv_bfloat16*)pTh, (__nv_bfloat16*)pTl, (long long)B_*NT_*TD_/4);
    split_kernel<<<1024, 256>>>(W,   (__nv_bfloat16*)pWh, (__nv_bfloat16*)pWl, (long long)TD_*TD_/4);

    // GEMM1: k = visual @ W^T -> bf16 hi/lo   (M=16384, N=1024, K=1024)
    GemmArgs a1{};
    a1.Ah = (const __nv_bfloat16*)pVh; a1.Al = (const __nv_bfloat16*)pVl;
    a1.Bh = (const __nv_bfloat16*)pWh; a1.Bl = (const __nv_bfloat16*)pWl;
    a1.Ch = (__nv_bfloat16*)pKh; a1.Cl = (__nv_bfloat16*)pKl;
    a1.lda = 1024; a1.ldb = 1024; a1.ldc = 1024;
    a1.K = 1024; a1.HZ = 1;
    gemm_bf16split<<<dim3(128, 8, 1), 256, SMEM_GEMM>>>(a1);

    // kT (hi/lo) for GEMM3 B operand
    transpose_bf16_kernel<<<dim3(128, 4, 32), dim3(32, 8)>>>((const __nv_bfloat16*)pKh, (__nv_bfloat16*)pKTh);
    transpose_bf16_kernel<<<dim3(128, 4, 32), dim3(32, 8)>>>((const __nv_bfloat16*)pKl, (__nv_bfloat16*)pKTl);

    // GEMM2: sim = q . k  (per z=(b,h): M=1024, N=4096, K=128)
    GemmArgs a2{};
    a2.Ah = (const __nv_bfloat16*)pTh; a2.Al = (const __nv_bfloat16*)pTl;
    a2.Bh = (const __nv_bfloat16*)pKh; a2.Bl = (const __nv_bfloat16*)pKl;
    a2.C = attn;
    a2.lda = 1024; a2.ldb = 1024; a2.ldc = 4096;
    a2.sAb = (long long)NT_*TD_;    a2.sAh = 128;
    a2.sBb = (long long)NV_*TD_;    a2.sBh = 128;
    a2.sCb = (long long)H_*NT_*NV_; a2.sCh = (long long)NT_*NV_;
    a2.K = 128; a2.HZ = 8;
    gemm_bf16split<<<dim3(8, 32, 32), 256, SMEM_GEMM>>>(a2);

    // Softmax in place + bf16 hi/lo split of attn
    softmax_split_kernel<<<B_*H_*NT_, 256>>>(attn, (__nv_bfloat16*)pPh, (__nv_bfloat16*)pPl);

    // GEMM3: out = attn @ k  (per z=(b,h): M=1024, N=128, K=4096)
    GemmArgs a3{};
    a3.Ah = (const __nv_bfloat16*)pPh; a3.Al = (const __nv_bfloat16*)pPl;
    a3.Bh = (const __nv_bfloat16*)pKTh; a3.Bl = (const __nv_bfloat16*)pKTl;
    a3.C = out;
    a3.lda = 4096; a3.ldb = 4096; a3.ldc = 1024;
    a3.sAb = (long long)H_*NT_*NV_; a3.sAh = (long long)NT_*NV_;
    a3.sBb = (long long)H_*D_*NV_;  a3.sBh = (long long)D_*NV_;
    a3.sCb = (long long)NT_*TD_;    a3.sCh = 128;
    a3.K = 4096; a3.HZ = 8;
    gemm_bf16split<<<dim3(8, 1, 32), 256, SMEM_GEMM>>>(a3);
}

// round 4
// speedup vs baseline: 1.0400x; 1.0400x over previous
#include <cuda_runtime.h>
#include <cuda_bf16.h>
#include <cstdint>

#define B_  4
#define NV_ 4096
#define NT_ 1024
#define TD_ 1024
#define H_  8
#define D_  128

// ------------------------- scratch (device globals) -------------------------
__device__ __align__(256) __nv_bfloat16 g_Vh[(size_t)B_*NV_*TD_];
__device__ __align__(256) __nv_bfloat16 g_Vl[(size_t)B_*NV_*TD_];
__device__ __align__(256) __nv_bfloat16 g_Th[(size_t)B_*NT_*TD_];
__device__ __align__(256) __nv_bfloat16 g_Tl[(size_t)B_*NT_*TD_];
__device__ __align__(256) __nv_bfloat16 g_Wh[(size_t)TD_*TD_];
__device__ __align__(256) __nv_bfloat16 g_Wl[(size_t)TD_*TD_];
__device__ __align__(256) __nv_bfloat16 g_Kh[(size_t)B_*NV_*TD_];
__device__ __align__(256) __nv_bfloat16 g_Kl[(size_t)B_*NV_*TD_];
__device__ __align__(256) __nv_bfloat16 g_Ph[(size_t)B_*H_*NT_*NV_];
__device__ __align__(256) __nv_bfloat16 g_Pl[(size_t)B_*H_*NT_*NV_];

// ------------------------------- helpers ------------------------------------
__device__ __forceinline__ uint32_t smem_u32(const void* p){
    uint32_t a;
    asm("{ .reg .u64 t; cvta.to.shared.u64 t, %1; cvt.u32.u64 %0, t; }" : "=r"(a) : "l"(p));
    return a;
}
__device__ __forceinline__ void cp16(uint32_t dst, const void* src){
    asm volatile("cp.async.cg.shared.global [%0], [%1], 16;" :: "r"(dst), "l"(src));
}
__device__ __forceinline__ void ldsm4(uint32_t* r, uint32_t addr){
    asm volatile("ldmatrix.sync.aligned.m8n8.x4.shared.b16 {%0,%1,%2,%3}, [%4];"
                 : "=r"(r[0]), "=r"(r[1]), "=r"(r[2]), "=r"(r[3]) : "r"(addr));
}
__device__ __forceinline__ void ldsm4t(uint32_t* r, uint32_t addr){
    asm volatile("ldmatrix.sync.aligned.m8n8.x4.trans.shared.b16 {%0,%1,%2,%3}, [%4];"
                 : "=r"(r[0]), "=r"(r[1]), "=r"(r[2]), "=r"(r[3]) : "r"(addr));
}
__device__ __forceinline__ void mma16816(float* c, const uint32_t* a, const uint32_t* b){
    asm volatile("mma.sync.aligned.m16n8k16.row.col.f32.bf16.bf16.f32 "
                 "{%0,%1,%2,%3}, {%4,%5,%6,%7}, {%8,%9}, {%0,%1,%2,%3};"
                 : "+f"(c[0]), "+f"(c[1]), "+f"(c[2]), "+f"(c[3])
                 : "r"(a[0]), "r"(a[1]), "r"(a[2]), "r"(a[3]), "r"(b[0]), "r"(b[1]));
}
__device__ __forceinline__ void split2(float x, float y, uint32_t& hp, uint32_t& lp){
    __nv_bfloat16 h0 = __float2bfloat16(x), h1 = __float2bfloat16(y);
    __nv_bfloat16 l0 = __float2bfloat16(x - __bfloat162float(h0));
    __nv_bfloat16 l1 = __float2bfloat16(y - __bfloat162float(h1));
    hp = (uint32_t)__bfloat16_as_ushort(h0) | ((uint32_t)__bfloat16_as_ushort(h1) << 16);
    lp = (uint32_t)__bfloat16_as_ushort(l0) | ((uint32_t)__bfloat16_as_ushort(l1) << 16);
}

// ------------------------- fp32 -> bf16 hi/lo split --------------------------
__global__ void split_kernel(const float* __restrict__ s, __nv_bfloat16* __restrict__ h,
                             __nv_bfloat16* __restrict__ l, long long n4){
    long long i = (long long)blockIdx.x * blockDim.x + threadIdx.x;
    long long stride = (long long)gridDim.x * blockDim.x;
    for (; i < n4; i += stride){
        float4 f = reinterpret_cast<const float4*>(s)[i];
        uint32_t h0, l0, h1, l1;
        split2(f.x, f.y, h0, l0);
        split2(f.z, f.w, h1, l1);
        reinterpret_cast<uint2*>(h)[i] = make_uint2(h0, h1);
        reinterpret_cast<uint2*>(l)[i] = make_uint2(l0, l1);
    }
}

// ---------------------------------------------------------------------------
// bf16 split-3 GEMM: C[128m,128n] = (Ah+Al)[M,K] * (Bh+Bl)^T
//  TRANSB=false: B stored [N rows, K cols] (K-major)   -> ldmatrix
//  TRANSB=true : B stored [K rows, N cols] (N-major)   -> ldmatrix.trans
// 256 threads = 8 warps (2m x 4n), warp tile 64x32, K-chunk 64,
// 3-stage cp.async ring, one __syncthreads per k-iter.
// ---------------------------------------------------------------------------
struct GemmArgs {
    const __nv_bfloat16 *Ah, *Al, *Bh, *Bl;
    float* C; __nv_bfloat16 *Ch, *Cl;
    long long lda, ldb, ldc;
    long long sAb, sAh, sBb, sBh, sCb, sCh;
    int K, HZ;
};

#define T_AH 0
#define T_AL 16384
#define T_BH 32768
#define T_BL 49152
#define STAGE 65536
#define SMEM_GEMM (3*STAGE)

template<bool TRANSB>
__global__ void __launch_bounds__(256, 1) gemm_bf16split(GemmArgs g){
    extern __shared__ char smem[];
    const uint32_t sb = smem_u32(smem);
    const int tid = threadIdx.x;
    const int lane = tid & 31, wid = tid >> 5;
    const int wm = wid >> 2, wn = wid & 3;

    const int zb = blockIdx.z / g.HZ, zh = blockIdx.z % g.HZ;
    const long long m0 = (long long)blockIdx.x << 7;
    const long long n0 = (long long)blockIdx.y << 7;
    const __nv_bfloat16* Ah = g.Ah + (long long)zb*g.sAb + (long long)zh*g.sAh + m0*g.lda;
    const __nv_bfloat16* Al = g.Al + (long long)zb*g.sAb + (long long)zh*g.sAh + m0*g.lda;
    const long long bofs = (long long)zb*g.sBb + (long long)zh*g.sBh + (TRANSB ? n0 : n0*g.ldb);
    const __nv_bfloat16* Bh = g.Bh + bofs;
    const __nv_bfloat16* Bl = g.Bl + bofs;

    float acc[4][4][4];
    #pragma unroll
    for (int a = 0; a < 4; ++a)
        #pragma unroll
        for (int b = 0; b < 4; ++b)
            #pragma unroll
            for (int c = 0; c < 4; ++c) acc[a][b][c] = 0.f;

    const int nkt = g.K >> 6;

    auto load_stage = [&](int S, int kt2){
        const uint32_t sbs = sb + (uint32_t)S * STAGE;
        const long long K0 = (long long)kt2 << 6;
        // A tile: 128 rows x 64 K-cols (8 x 16B granules per row)
        {
            const int r0 = tid >> 3, gc = tid & 7;
            #pragma unroll
            for (int i = 0; i < 4; ++i){
                int row = r0 + (i << 5);
                uint32_t off = (uint32_t)(row << 7) + (uint32_t)((gc ^ (row & 7)) << 4);
                long long ea = (long long)row * g.lda + K0 + (gc << 3);
                cp16(sbs + T_AH + off, Ah + ea);
                cp16(sbs + T_AL + off, Al + ea);
            }
        }
        if constexpr (!TRANSB){
            // B tile: 128 N-rows x 64 K-cols
            const int r0 = tid >> 3, gc = tid & 7;
            #pragma unroll
            for (int i = 0; i < 4; ++i){
                int row = r0 + (i << 5);
                uint32_t off = (uint32_t)(row << 7) + (uint32_t)((gc ^ (row & 7)) << 4);
                long long eb = (long long)row * g.ldb + K0 + (gc << 3);
                cp16(sbs + T_BH + off, Bh + eb);
                cp16(sbs + T_BL + off, Bl + eb);
            }
        } else {
            // B tile: 64 K-rows x 128 N-cols (16 x 16B granules per row)
            const int r0 = tid >> 4, bc = tid & 15;
            #pragma unroll
            for (int i = 0; i < 4; ++i){
                int row = r0 + (i << 4);
                uint32_t off = (uint32_t)(row << 8) + (uint32_t)((bc ^ (row & 7)) << 4);
                long long eb = (K0 + row) * g.ldb + (bc << 3);
                cp16(sbs + T_BH + off, Bh + eb);
                cp16(sbs + T_BL + off, Bl + eb);
            }
        }
    };

    // Prologue: stages 0 and 1
    load_stage(0, 0);
    asm volatile("cp.async.commit_group;" ::: "memory");
    if (nkt > 1) load_stage(1, 1);
    asm volatile("cp.async.commit_group;" ::: "memory");

    for (int kt = 0; kt < nkt; ++kt){
        asm volatile("cp.async.wait_group 1;" ::: "memory");
        __syncthreads();
        if (kt + 2 < nkt) load_stage((kt + 2) % 3, kt + 2);
        asm volatile("cp.async.commit_group;" ::: "memory");

        const uint32_t st = sb + (uint32_t)(kt % 3) * STAGE;
        #pragma unroll
        for (int s16 = 0; s16 < 4; ++s16){
            uint32_t afh[4][4], afl[4][4];
            const int arow0 = (wm << 6) + (lane & 15);
            const int ahalf = lane >> 4;
            #pragma unroll
            for (int mb = 0; mb < 4; ++mb){
                int row = arow0 + (mb << 4);
                uint32_t gc = (uint32_t)(((s16 << 1) + ahalf) ^ (row & 7));
                uint32_t ad = st + (uint32_t)(row << 7) + (gc << 4);
                ldsm4(afh[mb], ad + T_AH);
                ldsm4(afl[mb], ad + T_AL);
            }
            uint32_t bfh[4][2], bfl[4][2];
            if constexpr (!TRANSB){
                const int brow_ = (lane & 7) + ((lane >> 4) << 3);
                const int bhalf = (lane >> 3) & 1;
                #pragma unroll
                for (int bg = 0; bg < 2; ++bg){
                    int row = (wn << 5) + (bg << 4) + brow_;
                    uint32_t gc = (uint32_t)(((s16 << 1) + bhalf) ^ (row & 7));
                    uint32_t bd = st + (uint32_t)(row << 7) + (gc << 4);
                    uint32_t rh[4], rl[4];
                    ldsm4(rh, bd + T_BH);
                    ldsm4(rl, bd + T_BL);
                    bfh[bg*2+0][0] = rh[0]; bfh[bg*2+0][1] = rh[1];
                    bfh[bg*2+1][0] = rh[2]; bfh[bg*2+1][1] = rh[3];
                    bfl[bg*2+0][0] = rl[0]; bfl[bg*2+0][1] = rl[1];
                    bfl[bg*2+1][0] = rl[2]; bfl[bg*2+1][1] = rl[3];
                }
            } else {
                #pragma unroll
                for (int ng = 0; ng < 2; ++ng){
                    int row = (s16 << 4) + (lane & 15);
                    uint32_t nch = (uint32_t)((wn << 2) + (ng << 1) + (lane >> 4));
                    uint32_t bd = st + (uint32_t)(row << 8) + ((nch ^ (uint32_t)(row & 7)) << 4);
                    uint32_t rh[4], rl[4];
                    ldsm4t(rh, bd + T_BH);
                    ldsm4t(rl, bd + T_BL);
                    bfh[ng*2+0][0] = rh[0]; bfh[ng*2+0][1] = rh[1];
                    bfh[ng*2+1][0] = rh[2]; bfh[ng*2+1][1] = rh[3];
                    bfl[ng*2+0][0] = rl[0]; bfl[ng*2+0][1] = rl[1];
                    bfl[ng*2+1][0] = rl[2]; bfl[ng*2+1][1] = rl[3];
                }
            }
            #pragma unroll
            for (int mb = 0; mb < 4; ++mb)
                #pragma unroll
                for (int nb = 0; nb < 4; ++nb){
                    mma16816(acc[mb][nb], afh[mb], bfh[nb]);
                    mma16816(acc[mb][nb], afh[mb], bfl[nb]);
                    mma16816(acc[mb][nb], afl[mb], bfh[nb]);
                }
        }
    }

    // ---- epilogue ----
    const int trow = lane >> 2, tcol = (lane & 3) << 1;
    const long long cbase = (long long)zb*g.sCb + (long long)zh*g.sCh;
    #pragma unroll
    for (int mb = 0; mb < 4; ++mb){
        #pragma unroll
        for (int nb = 0; nb < 4; ++nb){
            long long r0 = m0 + (wm << 6) + (mb << 4) + trow;
            long long cc = n0 + (wn << 5) + (nb << 3) + tcol;
            float* a4 = acc[mb][nb];
            if (g.C){
                *reinterpret_cast<float2*>(g.C + cbase + r0*g.ldc + cc) = make_float2(a4[0], a4[1]);
                *reinterpret_cast<float2*>(g.C + cbase + (r0+8)*g.ldc + cc) = make_float2(a4[2], a4[3]);
            } else {
                uint32_t hp, lp;
                split2(a4[0], a4[1], hp, lp);
                *reinterpret_cast<uint32_t*>(g.Ch + cbase + r0*g.ldc + cc) = hp;
                *reinterpret_cast<uint32_t*>(g.Cl + cbase + r0*g.ldc + cc) = lp;
                split2(a4[2], a4[3], hp, lp);
                *reinterpret_cast<uint32_t*>(g.Ch + cbase + (r0+8)*g.ldc + cc) = hp;
                *reinterpret_cast<uint32_t*>(g.Cl + cbase + (r0+8)*g.ldc + cc) = lp;
            }
        }
    }
}

// -------- softmax over 4096 cols, in place + bf16 hi/lo split emission ------
__global__ void softmax_split_kernel(float* __restrict__ attn,
                                     __nv_bfloat16* __restrict__ ph,
                                     __nv_bfloat16* __restrict__ pl){
    __shared__ float red[256];
    const long long row = blockIdx.x;
    float* p = attn + row * 4096;
    __nv_bfloat16* hh = ph + row * 4096;
    __nv_bfloat16* ll = pl + row * 4096;
    const int t = threadIdx.x;
    float v[16];
    float mx = -3.402823466e38f;
    #pragma unroll
    for (int i = 0; i < 16; ++i){ v[i] = p[t + i*256]; mx = fmaxf(mx, v[i]); }
    red[t] = mx; __syncthreads();
    #pragma unroll
    for (int s = 128; s > 0; s >>= 1){
        if (t < s) red[t] = fmaxf(red[t], red[t + s]);
        __syncthreads();
    }
    mx = red[0]; __syncthreads();
    float sum = 0.f;
    #pragma unroll
    for (int i = 0; i < 16; ++i){ v[i] = expf(v[i] - mx); sum += v[i]; }
    red[t] = sum; __syncthreads();
    #pragma unroll
    for (int s = 128; s > 0; s >>= 1){
        if (t < s) red[t] += red[t + s];
        __syncthreads();
    }
    const float inv = 1.0f / red[0];
    #pragma unroll
    for (int i = 0; i < 16; ++i){
        float a = v[i] * inv;
        p[t + i*256] = a;
        __nv_bfloat16 h = __float2bfloat16(a);
        hh[t + i*256] = h;
        ll[t + i*256] = __float2bfloat16(a - __bfloat162float(h));
    }
}

// ---------------------------------------------------------------------------
extern "C" void kernel_launch(void* const* d_in, const int* in_sizes, int n_in,
                              void* d_out, int out_size){
    const float* vis = (const float*)d_in[0];   // [B, NV, 1024]
    const float* txt = (const float*)d_in[1];   // [B, NT, 1024]
    const float* W   = (const float*)d_in[2];   // [1024, 1024]
    float* out  = (float*)d_out;                          // [B, NT, TD]
    float* attn = out + (size_t)B_*NT_*TD_;               // [B, H, NT, NV]

    void *pVh,*pVl,*pTh,*pTl,*pWh,*pWl,*pKh,*pKl,*pPh,*pPl;
    cudaGetSymbolAddress(&pVh, g_Vh);  cudaGetSymbolAddress(&pVl, g_Vl);
    cudaGetSymbolAddress(&pTh, g_Th);  cudaGetSymbolAddress(&pTl, g_Tl);
    cudaGetSymbolAddress(&pWh, g_Wh);  cudaGetSymbolAddress(&pWl, g_Wl);
    cudaGetSymbolAddress(&pKh, g_Kh);  cudaGetSymbolAddress(&pKl, g_Kl);
    cudaGetSymbolAddress(&pPh, g_Ph);  cudaGetSymbolAddress(&pPl, g_Pl);

    cudaFuncSetAttribute(gemm_bf16split<false>,
                         cudaFuncAttributeMaxDynamicSharedMemorySize, SMEM_GEMM);
    cudaFuncSetAttribute(gemm_bf16split<true>,
                         cudaFuncAttributeMaxDynamicSharedMemorySize, SMEM_GEMM);

    // Split inputs to bf16 hi/lo
    split_kernel<<<8192, 256>>>(vis, (__nv_bfloat16*)pVh, (__nv_bfloat16*)pVl, (long long)B_*NV_*TD_/4);
    split_kernel<<<4096, 256>>>(txt, (__nv_bfloat16*)pTh, (__nv_bfloat16*)pTl, (long long)B_*NT_*TD_/4);
    split_kernel<<<1024, 256>>>(W,   (__nv_bfloat16*)pWh, (__nv_bfloat16*)pWl, (long long)TD_*TD_/4);

    // GEMM1: k = visual @ W^T -> bf16 hi/lo   (M=16384, N=1024, K=1024)
    GemmArgs a1{};
    a1.Ah = (const __nv_bfloat16*)pVh; a1.Al = (const __nv_bfloat16*)pVl;
    a1.Bh = (const __nv_bfloat16*)pWh; a1.Bl = (const __nv_bfloat16*)pWl;
    a1.Ch = (__nv_bfloat16*)pKh; a1.Cl = (__nv_bfloat16*)pKl;
    a1.lda = 1024; a1.ldb = 1024; a1.ldc = 1024;
    a1.K = 1024; a1.HZ = 1;
    gemm_bf16split<false><<<dim3(128, 8, 1), 256, SMEM_GEMM>>>(a1);

    // GEMM2: sim = q . k  (per z=(b,h): M=1024, N=4096, K=128)
    GemmArgs a2{};
    a2.Ah = (const __nv_bfloat16*)pTh; a2.Al = (const __nv_bfloat16*)pTl;
    a2.Bh = (const __nv_bfloat16*)pKh; a2.Bl = (const __nv_bfloat16*)pKl;
    a2.C = attn;
    a2.lda = 1024; a2.ldb = 1024; a2.ldc = 4096;
    a2.sAb = (long long)NT_*TD_;    a2.sAh = 128;
    a2.sBb = (long long)NV_*TD_;    a2.sBh = 128;
    a2.sCb = (long long)H_*NT_*NV_; a2.sCh = (long long)NT_*NV_;
    a2.K = 128; a2.HZ = 8;
    gemm_bf16split<false><<<dim3(8, 32, 32), 256, SMEM_GEMM>>>(a2);

    // Softmax in place + bf16 hi/lo split of attn
    softmax_split_kernel<<<B_*H_*NT_, 256>>>(attn, (__nv_bfloat16*)pPh, (__nv_bfloat16*)pPl);

    // GEMM3: out = attn @ k  (per z=(b,h): M=1024, N=128, K=4096), B N-major
    GemmArgs a3{};
    a3.Ah = (const __nv_bfloat16*)pPh; a3.Al = (const __nv_bfloat16*)pPl;
    a3.Bh = (const __nv_bfloat16*)pKh; a3.Bl = (const __nv_bfloat16*)pKl;
    a3.C = out;
    a3.lda = 4096; a3.ldb = 1024; a3.ldc = 1024;
    a3.sAb = (long long)H_*NT_*NV_; a3.sAh = (long long)NT_*NV_;
    a3.sBb = (long long)NV_*TD_;    a3.sBh = 128;
    a3.sCb = (long long)NT_*TD_;    a3.sCh = 128;
    a3.K = 4096; a3.HZ = 8;
    gemm_bf16split<true><<<dim3(8, 1, 32), 256, SMEM_GEMM>>>(a3);
}

// round 5
// speedup vs baseline: 1.0568x; 1.0162x over previous
#include <cuda_runtime.h>
#include <cuda_bf16.h>
#include <cstdint>

#define B_  4
#define NV_ 4096
#define NT_ 1024
#define TD_ 1024
#define H_  8
#define D_  128

// ------------------------- scratch (device globals) -------------------------
__device__ __align__(256) __nv_bfloat16 g_Vh[(size_t)B_*NV_*TD_];
__device__ __align__(256) __nv_bfloat16 g_Vl[(size_t)B_*NV_*TD_];
__device__ __align__(256) __nv_bfloat16 g_Th[(size_t)B_*NT_*TD_];
__device__ __align__(256) __nv_bfloat16 g_Tl[(size_t)B_*NT_*TD_];
__device__ __align__(256) __nv_bfloat16 g_Wh[(size_t)TD_*TD_];
__device__ __align__(256) __nv_bfloat16 g_Wl[(size_t)TD_*TD_];
__device__ __align__(256) __nv_bfloat16 g_Kh[(size_t)B_*NV_*TD_];
__device__ __align__(256) __nv_bfloat16 g_Kl[(size_t)B_*NV_*TD_];

// ------------------------------- helpers ------------------------------------
__device__ __forceinline__ uint32_t smem_u32(const void* p){
    uint32_t a;
    asm("{ .reg .u64 t; cvta.to.shared.u64 t, %1; cvt.u32.u64 %0, t; }" : "=r"(a) : "l"(p));
    return a;
}
__device__ __forceinline__ void cp16(uint32_t dst, const void* src){
    asm volatile("cp.async.cg.shared.global [%0], [%1], 16;" :: "r"(dst), "l"(src));
}
__device__ __forceinline__ void ldsm4(uint32_t* r, uint32_t addr){
    asm volatile("ldmatrix.sync.aligned.m8n8.x4.shared.b16 {%0,%1,%2,%3}, [%4];"
                 : "=r"(r[0]), "=r"(r[1]), "=r"(r[2]), "=r"(r[3]) : "r"(addr));
}
__device__ __forceinline__ void ldsm4t(uint32_t* r, uint32_t addr){
    asm volatile("ldmatrix.sync.aligned.m8n8.x4.trans.shared.b16 {%0,%1,%2,%3}, [%4];"
                 : "=r"(r[0]), "=r"(r[1]), "=r"(r[2]), "=r"(r[3]) : "r"(addr));
}
__device__ __forceinline__ void mma16816(float* c, const uint32_t* a, const uint32_t* b){
    asm volatile("mma.sync.aligned.m16n8k16.row.col.f32.bf16.bf16.f32 "
                 "{%0,%1,%2,%3}, {%4,%5,%6,%7}, {%8,%9}, {%0,%1,%2,%3};"
                 : "+f"(c[0]), "+f"(c[1]), "+f"(c[2]), "+f"(c[3])
                 : "r"(a[0]), "r"(a[1]), "r"(a[2]), "r"(a[3]), "r"(b[0]), "r"(b[1]));
}
__device__ __forceinline__ void split2(float x, float y, uint32_t& hp, uint32_t& lp){
    __nv_bfloat16 h0 = __float2bfloat16(x), h1 = __float2bfloat16(y);
    __nv_bfloat16 l0 = __float2bfloat16(x - __bfloat162float(h0));
    __nv_bfloat16 l1 = __float2bfloat16(y - __bfloat162float(h1));
    hp = (uint32_t)__bfloat16_as_ushort(h0) | ((uint32_t)__bfloat16_as_ushort(h1) << 16);
    lp = (uint32_t)__bfloat16_as_ushort(l0) | ((uint32_t)__bfloat16_as_ushort(l1) << 16);
}

// ------------------------- fp32 -> bf16 hi/lo split --------------------------
__global__ void split_kernel(const float* __restrict__ s, __nv_bfloat16* __restrict__ h,
                             __nv_bfloat16* __restrict__ l, long long n4){
    long long i = (long long)blockIdx.x * blockDim.x + threadIdx.x;
    long long stride = (long long)gridDim.x * blockDim.x;
    for (; i < n4; i += stride){
        float4 f = reinterpret_cast<const float4*>(s)[i];
        uint32_t h0, l0, h1, l1;
        split2(f.x, f.y, h0, l0);
        split2(f.z, f.w, h1, l1);
        reinterpret_cast<uint2*>(h)[i] = make_uint2(h0, h1);
        reinterpret_cast<uint2*>(l)[i] = make_uint2(l0, l1);
    }
}

// ---------------------------------------------------------------------------
// bf16 split-3 GEMM: C[128m,128n] = (Ah+Al)[M,K] * (Bh+Bl)^T
//  TRANSB=false: A/B pre-split bf16 pairs, both K-major, cp.async, frag dbuf.
//  TRANSB=true : A is fp32 (split on the fly, LDG reg-prefetch + STS),
//                B stored [K rows, N cols] (N-major) -> ldmatrix.trans.
// 256 threads = 8 warps (2m x 4n), warp tile 64x32, K-chunk 64, 3-stage ring.
// ---------------------------------------------------------------------------
struct GemmArgs {
    const __nv_bfloat16 *Ah, *Al, *Bh, *Bl;
    const float* Af32;
    float* C; __nv_bfloat16 *Ch, *Cl;
    long long lda, ldb, ldc;
    long long sAb, sAh, sBb, sBh, sCb, sCh;
    int K, HZ;
};

#define T_AH 0
#define T_AL 16384
#define T_BH 32768
#define T_BL 49152
#define STAGE 65536
#define SMEM_GEMM (3*STAGE)

template<bool TRANSB>
__global__ void __launch_bounds__(256, 1) gemm_bf16split(GemmArgs g){
    extern __shared__ char smem[];
    const uint32_t sb = smem_u32(smem);
    const int tid = threadIdx.x;
    const int lane = tid & 31, wid = tid >> 5;
    const int wm = wid >> 2, wn = wid & 3;

    const int zb = blockIdx.z / g.HZ, zh = blockIdx.z % g.HZ;
    const long long m0 = (long long)blockIdx.x << 7;
    const long long n0 = (long long)blockIdx.y << 7;
    const long long aoff = (long long)zb*g.sAb + (long long)zh*g.sAh + m0*g.lda;
    const __nv_bfloat16* Ah = g.Ah ? g.Ah + aoff : nullptr;
    const __nv_bfloat16* Al = g.Al ? g.Al + aoff : nullptr;
    const float* Af32 = TRANSB ? g.Af32 + aoff : nullptr;
    const long long bofs = (long long)zb*g.sBb + (long long)zh*g.sBh + (TRANSB ? n0 : n0*g.ldb);
    const __nv_bfloat16* Bh = g.Bh + bofs;
    const __nv_bfloat16* Bl = g.Bl + bofs;

    float acc[4][4][4];
    #pragma unroll
    for (int a = 0; a < 4; ++a)
        #pragma unroll
        for (int b = 0; b < 4; ++b)
            #pragma unroll
            for (int c = 0; c < 4; ++c) acc[a][b][c] = 0.f;

    const int nkt = g.K >> 6;

    // ---- SMEM stage loaders ----
    auto loadA_pairs = [&](int S, int kt2){            // !TRANSB: A bf16 pairs
        const uint32_t sbs = sb + (uint32_t)S * STAGE;
        const long long K0 = (long long)kt2 << 6;
        const int r0 = tid >> 3, gc = tid & 7;
        #pragma unroll
        for (int i = 0; i < 4; ++i){
            int row = r0 + (i << 5);
            uint32_t off = (uint32_t)(row << 7) + (uint32_t)((gc ^ (row & 7)) << 4);
            long long ea = (long long)row * g.lda + K0 + (gc << 3);
            cp16(sbs + T_AH + off, Ah + ea);
            cp16(sbs + T_AL + off, Al + ea);
        }
    };
    auto loadB = [&](int S, int kt2){
        const uint32_t sbs = sb + (uint32_t)S * STAGE;
        const long long K0 = (long long)kt2 << 6;
        if constexpr (!TRANSB){
            const int r0 = tid >> 3, gc = tid & 7;
            #pragma unroll
            for (int i = 0; i < 4; ++i){
                int row = r0 + (i << 5);
                uint32_t off = (uint32_t)(row << 7) + (uint32_t)((gc ^ (row & 7)) << 4);
                long long eb = (long long)row * g.ldb + K0 + (gc << 3);
                cp16(sbs + T_BH + off, Bh + eb);
                cp16(sbs + T_BL + off, Bl + eb);
            }
        } else {
            const int r0 = tid >> 4, bc = tid & 15;
            #pragma unroll
            for (int i = 0; i < 4; ++i){
                int row = r0 + (i << 4);
                uint32_t off = (uint32_t)(row << 8) + (uint32_t)((bc ^ (row & 7)) << 4);
                long long eb = (K0 + row) * g.ldb + (bc << 3);
                cp16(sbs + T_BH + off, Bh + eb);
                cp16(sbs + T_BL + off, Bl + eb);
            }
        }
    };
    // TRANSB A path: fp32 LDG into regs, later split+STS
    float4 ra[8];
    auto ldA = [&](int kt2){
        const long long K0 = (long long)kt2 << 6;
        #pragma unroll
        for (int i = 0; i < 8; ++i){
            int lin = tid + (i << 8);
            int row = lin >> 4, c4 = lin & 15;
            ra[i] = *reinterpret_cast<const float4*>(Af32 + (long long)row*g.lda + K0 + (c4 << 2));
        }
    };
    auto stA = [&](int S){
        char* base = smem + (size_t)S * STAGE;
        #pragma unroll
        for (int i = 0; i < 8; ++i){
            int lin = tid + (i << 8);
            int row = lin >> 4, c4 = lin & 15;
            uint32_t h0, l0, h1, l1;
            split2(ra[i].x, ra[i].y, h0, l0);
            split2(ra[i].z, ra[i].w, h1, l1);
            uint32_t off = (uint32_t)(row << 7)
                         + ((uint32_t)((c4 >> 1) ^ (row & 7)) << 4)
                         + ((uint32_t)(c4 & 1) << 3);
            *reinterpret_cast<uint2*>(base + T_AH + off) = make_uint2(h0, h1);
            *reinterpret_cast<uint2*>(base + T_AL + off) = make_uint2(l0, l1);
        }
    };

    // ---- fragment loaders ----
    auto load_fragsA = [&](uint32_t st, int s16, uint32_t (&fah)[4][4], uint32_t (&fal)[4][4]){
        const int arow0 = (wm << 6) + (lane & 15);
        const int ahalf = lane >> 4;
        #pragma unroll
        for (int mb = 0; mb < 4; ++mb){
            int row = arow0 + (mb << 4);
            uint32_t gc = (uint32_t)(((s16 << 1) + ahalf) ^ (row & 7));
            uint32_t ad = st + (uint32_t)(row << 7) + (gc << 4);
            ldsm4(fah[mb], ad + T_AH);
            ldsm4(fal[mb], ad + T_AL);
        }
    };
    auto load_fragsB = [&](uint32_t st, int s16, uint32_t (&fbh)[4][2], uint32_t (&fbl)[4][2]){
        if constexpr (!TRANSB){
            const int brow_ = (lane & 7) + ((lane >> 4) << 3);
            const int bhalf = (lane >> 3) & 1;
            #pragma unroll
            for (int bg = 0; bg < 2; ++bg){
                int row = (wn << 5) + (bg << 4) + brow_;
                uint32_t gc = (uint32_t)(((s16 << 1) + bhalf) ^ (row & 7));
                uint32_t bd = st + (uint32_t)(row << 7) + (gc << 4);
                uint32_t rh[4], rl[4];
                ldsm4(rh, bd + T_BH);
                ldsm4(rl, bd + T_BL);
                fbh[bg*2+0][0] = rh[0]; fbh[bg*2+0][1] = rh[1];
                fbh[bg*2+1][0] = rh[2]; fbh[bg*2+1][1] = rh[3];
                fbl[bg*2+0][0] = rl[0]; fbl[bg*2+0][1] = rl[1];
                fbl[bg*2+1][0] = rl[2]; fbl[bg*2+1][1] = rl[3];
            }
        } else {
            #pragma unroll
            for (int ng = 0; ng < 2; ++ng){
                int row = (s16 << 4) + (lane & 15);
                uint32_t nch = (uint32_t)((wn << 2) + (ng << 1) + (lane >> 4));
                uint32_t bd = st + (uint32_t)(row << 8) + ((nch ^ (uint32_t)(row & 7)) << 4);
                uint32_t rh[4], rl[4];
                ldsm4t(rh, bd + T_BH);
                ldsm4t(rl, bd + T_BL);
                fbh[ng*2+0][0] = rh[0]; fbh[ng*2+0][1] = rh[1];
                fbh[ng*2+1][0] = rh[2]; fbh[ng*2+1][1] = rh[3];
                fbl[ng*2+0][0] = rl[0]; fbl[ng*2+0][1] = rl[1];
                fbl[ng*2+1][0] = rl[2]; fbl[ng*2+1][1] = rl[3];
            }
        }
    };

    // ---- prologue ----
    if constexpr (!TRANSB){
        loadA_pairs(0, 0); loadB(0, 0);
        asm volatile("cp.async.commit_group;" ::: "memory");
        if (nkt > 1){ loadA_pairs(1, 1); loadB(1, 1); }
        asm volatile("cp.async.commit_group;" ::: "memory");
    } else {
        ldA(0); stA(0); loadB(0, 0);
        asm volatile("cp.async.commit_group;" ::: "memory");
        if (nkt > 1){ ldA(1); stA(1); loadB(1, 1); }
        asm volatile("cp.async.commit_group;" ::: "memory");
        if (nkt > 2) ldA(2);
    }

    for (int kt = 0; kt < nkt; ++kt){
        asm volatile("cp.async.wait_group 1;" ::: "memory");
        __syncthreads();
        if constexpr (!TRANSB){
            if (kt + 2 < nkt){ loadA_pairs((kt + 2) % 3, kt + 2); loadB((kt + 2) % 3, kt + 2); }
            asm volatile("cp.async.commit_group;" ::: "memory");
        } else {
            if (kt + 2 < nkt){ stA((kt + 2) % 3); loadB((kt + 2) % 3, kt + 2); }
            asm volatile("cp.async.commit_group;" ::: "memory");
            if (kt + 3 < nkt) ldA(kt + 3);
        }

        const uint32_t st = sb + (uint32_t)(kt % 3) * STAGE;
        // register double-buffered fragments
        uint32_t aHf[2][4][4], aLf[2][4][4], bHf[2][4][2], bLf[2][4][2];
        load_fragsA(st, 0, aHf[0], aLf[0]);
        load_fragsB(st, 0, bHf[0], bLf[0]);
        #pragma unroll
        for (int s16 = 0; s16 < 4; ++s16){
            const int cur = s16 & 1;
            if (s16 < 3){
                load_fragsA(st, s16 + 1, aHf[cur ^ 1], aLf[cur ^ 1]);
                load_fragsB(st, s16 + 1, bHf[cur ^ 1], bLf[cur ^ 1]);
            }
            #pragma unroll
            for (int mb = 0; mb < 4; ++mb)
                #pragma unroll
                for (int nb = 0; nb < 4; ++nb){
                    mma16816(acc[mb][nb], aHf[cur][mb], bHf[cur][nb]);
                    mma16816(acc[mb][nb], aHf[cur][mb], bLf[cur][nb]);
                    mma16816(acc[mb][nb], aLf[cur][mb], bHf[cur][nb]);
                }
        }
    }

    // ---- epilogue ----
    const int trow = lane >> 2, tcol = (lane & 3) << 1;
    const long long cbase = (long long)zb*g.sCb + (long long)zh*g.sCh;
    #pragma unroll
    for (int mb = 0; mb < 4; ++mb){
        #pragma unroll
        for (int nb = 0; nb < 4; ++nb){
            long long r0 = m0 + (wm << 6) + (mb << 4) + trow;
            long long cc = n0 + (wn << 5) + (nb << 3) + tcol;
            float* a4 = acc[mb][nb];
            if (g.C){
                *reinterpret_cast<float2*>(g.C + cbase + r0*g.ldc + cc) = make_float2(a4[0], a4[1]);
                *reinterpret_cast<float2*>(g.C + cbase + (r0+8)*g.ldc + cc) = make_float2(a4[2], a4[3]);
            } else {
                uint32_t hp, lp;
                split2(a4[0], a4[1], hp, lp);
                *reinterpret_cast<uint32_t*>(g.Ch + cbase + r0*g.ldc + cc) = hp;
                *reinterpret_cast<uint32_t*>(g.Cl + cbase + r0*g.ldc + cc) = lp;
                split2(a4[2], a4[3], hp, lp);
                *reinterpret_cast<uint32_t*>(g.Ch + cbase + (r0+8)*g.ldc + cc) = hp;
                *reinterpret_cast<uint32_t*>(g.Cl + cbase + (r0+8)*g.ldc + cc) = lp;
            }
        }
    }
}

// -------------- softmax over 4096 cols, in place (fp32 only) ----------------
__global__ void softmax_kernel(float* __restrict__ attn){
    __shared__ float red[256];
    const long long row = blockIdx.x;
    float* p = attn + row * 4096;
    const int t = threadIdx.x;
    float v[16];
    float mx = -3.402823466e38f;
    #pragma unroll
    for (int i = 0; i < 16; ++i){ v[i] = p[t + i*256]; mx = fmaxf(mx, v[i]); }
    red[t] = mx; __syncthreads();
    #pragma unroll
    for (int s = 128; s > 0; s >>= 1){
        if (t < s) red[t] = fmaxf(red[t], red[t + s]);
        __syncthreads();
    }
    mx = red[0]; __syncthreads();
    float sum = 0.f;
    #pragma unroll
    for (int i = 0; i < 16; ++i){ v[i] = expf(v[i] - mx); sum += v[i]; }
    red[t] = sum; __syncthreads();
    #pragma unroll
    for (int s = 128; s > 0; s >>= 1){
        if (t < s) red[t] += red[t + s];
        __syncthreads();
    }
    const float inv = 1.0f / red[0];
    #pragma unroll
    for (int i = 0; i < 16; ++i) p[t + i*256] = v[i] * inv;
}

// ---------------------------------------------------------------------------
extern "C" void kernel_launch(void* const* d_in, const int* in_sizes, int n_in,
                              void* d_out, int out_size){
    const float* vis = (const float*)d_in[0];   // [B, NV, 1024]
    const float* txt = (const float*)d_in[1];   // [B, NT, 1024]
    const float* W   = (const float*)d_in[2];   // [1024, 1024]
    float* out  = (float*)d_out;                          // [B, NT, TD]
    float* attn = out + (size_t)B_*NT_*TD_;               // [B, H, NT, NV]

    void *pVh,*pVl,*pTh,*pTl,*pWh,*pWl,*pKh,*pKl;
    cudaGetSymbolAddress(&pVh, g_Vh);  cudaGetSymbolAddress(&pVl, g_Vl);
    cudaGetSymbolAddress(&pTh, g_Th);  cudaGetSymbolAddress(&pTl, g_Tl);
    cudaGetSymbolAddress(&pWh, g_Wh);  cudaGetSymbolAddress(&pWl, g_Wl);
    cudaGetSymbolAddress(&pKh, g_Kh);  cudaGetSymbolAddress(&pKl, g_Kl);

    cudaFuncSetAttribute(gemm_bf16split<false>,
                         cudaFuncAttributeMaxDynamicSharedMemorySize, SMEM_GEMM);
    cudaFuncSetAttribute(gemm_bf16split<true>,
                         cudaFuncAttributeMaxDynamicSharedMemorySize, SMEM_GEMM);

    // Split inputs to bf16 hi/lo
    split_kernel<<<8192, 256>>>(vis, (__nv_bfloat16*)pVh, (__nv_bfloat16*)pVl, (long long)B_*NV_*TD_/4);
    split_kernel<<<4096, 256>>>(txt, (__nv_bfloat16*)pTh, (__nv_bfloat16*)pTl, (long long)B_*NT_*TD_/4);
    split_kernel<<<1024, 256>>>(W,   (__nv_bfloat16*)pWh, (__nv_bfloat16*)pWl, (long long)TD_*TD_/4);

    // GEMM1: k = visual @ W^T -> bf16 hi/lo   (M=16384, N=1024, K=1024)
    GemmArgs a1{};
    a1.Ah = (const __nv_bfloat16*)pVh; a1.Al = (const __nv_bfloat16*)pVl;
    a1.Bh = (const __nv_bfloat16*)pWh; a1.Bl = (const __nv_bfloat16*)pWl;
    a1.Ch = (__nv_bfloat16*)pKh; a1.Cl = (__nv_bfloat16*)pKl;
    a1.lda = 1024; a1.ldb = 1024; a1.ldc = 1024;
    a1.K = 1024; a1.HZ = 1;
    gemm_bf16split<false><<<dim3(128, 8, 1), 256, SMEM_GEMM>>>(a1);

    // GEMM2: sim = q . k  (per z=(b,h): M=1024, N=4096, K=128)
    GemmArgs a2{};
    a2.Ah = (const __nv_bfloat16*)pTh; a2.Al = (const __nv_bfloat16*)pTl;
    a2.Bh = (const __nv_bfloat16*)pKh; a2.Bl = (const __nv_bfloat16*)pKl;
    a2.C = attn;
    a2.lda = 1024; a2.ldb = 1024; a2.ldc = 4096;
    a2.sAb = (long long)NT_*TD_;    a2.sAh = 128;
    a2.sBb = (long long)NV_*TD_;    a2.sBh = 128;
    a2.sCb = (long long)H_*NT_*NV_; a2.sCh = (long long)NT_*NV_;
    a2.K = 128; a2.HZ = 8;
    gemm_bf16split<false><<<dim3(8, 32, 32), 256, SMEM_GEMM>>>(a2);

    // Softmax in place (fp32 attn is both an output and GEMM3's A)
    softmax_kernel<<<B_*H_*NT_, 256>>>(attn);

    // GEMM3: out = attn @ k  (per z=(b,h): M=1024, N=128, K=4096)
    // A = fp32 attn, split on the fly; B = k (N-major view), ldmatrix.trans
    GemmArgs a3{};
    a3.Af32 = attn;
    a3.Bh = (const __nv_bfloat16*)pKh; a3.Bl = (const __nv_bfloat16*)pKl;
    a3.C = out;
    a3.lda = 4096; a3.ldb = 1024; a3.ldc = 1024;
    a3.sAb = (long long)H_*NT_*NV_; a3.sAh = (long long)NT_*NV_;
    a3.sBb = (long long)NV_*TD_;    a3.sBh = 128;
    a3.sCb = (long long)NT_*TD_;    a3.sCh = 128;
    a3.K = 4096; a3.HZ = 8;
    gemm_bf16split<true><<<dim3(8, 1, 32), 256, SMEM_GEMM>>>(a3);
}